// round 10
// baseline (speedup 1.0000x reference)
#include <cuda_runtime.h>
#include <cstdint>

// Problem constants
constexpr int Hd = 1024;   // hidden
constexpr int Ff = 4096;   // intermediate
constexpr int NE = 8;      // experts
constexpr int NT = 2048;   // tokens
constexpr int NA = 2 * NT; // assignments (top-2)

// ---------------- device scratch (no allocations allowed) ----------------
__device__ int   g_cnt[NE];
__device__ int   g_tok[NE][NT];
__device__ float g_wt[NE][NT];
__device__ int   g_slot[NE][NT];
__device__ float g_h[(size_t)NA * Ff];   // 64 MB fp32 intermediate, row = tok*2+slot
__device__ float g_sbuf[2 * NT * Hd];    // per-rank-slot output buffers

// ---------------- helpers ----------------
__device__ __forceinline__ float f2tf(float x) {
    unsigned u;
    asm("cvt.rna.tf32.f32 %0, %1;" : "=r"(u) : "f"(x));
    return __uint_as_float(u);
}
__device__ __forceinline__ void mma8(float c[4], const unsigned a[4], const unsigned b[2]) {
    asm volatile(
        "mma.sync.aligned.m16n8k8.row.col.f32.tf32.tf32.f32 "
        "{%0,%1,%2,%3},{%4,%5,%6,%7},{%8,%9},{%0,%1,%2,%3};"
        : "+f"(c[0]), "+f"(c[1]), "+f"(c[2]), "+f"(c[3])
        : "r"(a[0]), "r"(a[1]), "r"(a[2]), "r"(a[3]), "r"(b[0]), "r"(b[1]));
}

// ---------------- small kernels ----------------
__global__ void zero_kernel() {
    if (threadIdx.x < NE) g_cnt[threadIdx.x] = 0;
}

// One warp per token: logits -> softmax -> top-2 -> softmax of the two PROBS.
__global__ void router_kernel(const float* __restrict__ x, const float* __restrict__ gw) {
    int tok  = blockIdx.x * 8 + (threadIdx.x >> 5);
    int lane = threadIdx.x & 31;
    if (tok >= NT) return;
    const float* xr = x + (size_t)tok * Hd;

    float acc[NE];
#pragma unroll
    for (int e = 0; e < NE; e++) acc[e] = 0.f;
    for (int i = lane; i < Hd; i += 32) {
        float xv = xr[i];
        const float* g = gw + i * NE;
#pragma unroll
        for (int e = 0; e < NE; e++) acc[e] = fmaf(xv, g[e], acc[e]);
    }
#pragma unroll
    for (int e = 0; e < NE; e++) {
#pragma unroll
        for (int o = 16; o > 0; o >>= 1) acc[e] += __shfl_xor_sync(0xffffffffu, acc[e], o);
    }
    if (lane == 0) {
        float m = acc[0];
#pragma unroll
        for (int e = 1; e < NE; e++) m = fmaxf(m, acc[e]);
        float p[NE], s = 0.f;
#pragma unroll
        for (int e = 0; e < NE; e++) { p[e] = expf(acc[e] - m); s += p[e]; }
        float inv = 1.f / s;
#pragma unroll
        for (int e = 0; e < NE; e++) p[e] *= inv;

        int i0 = 0;
#pragma unroll
        for (int e = 1; e < NE; e++) if (p[e] > p[i0]) i0 = e;
        int i1 = (i0 == 0) ? 1 : 0;
#pragma unroll
        for (int e = 0; e < NE; e++) if (e != i0 && p[e] > p[i1]) i1 = e;

        float eb = expf(p[i1] - p[i0]);       // <= 1
        float w0 = 1.f / (1.f + eb);
        float w1 = 1.f - w0;

        int s0 = atomicAdd(&g_cnt[i0], 1);
        g_tok[i0][s0] = tok; g_wt[i0][s0] = w0; g_slot[i0][s0] = 0;
        int s1 = atomicAdd(&g_cnt[i1], 1);
        g_tok[i1][s1] = tok; g_wt[i1][s1] = w1; g_slot[i1][s1] = 1;
    }
}

// ============================================================================
// Layouts (identical to R9, conflict-free):
//  A smem: [128 rows][16 words], k at word 4*((k%4) ^ ((row>>1)&3)) + k/4.
//  B smem: [16 k-rows][pitch], pitch 136 (N=128) / 72 (N=64).
// Geometry (new): 128 threads, 4 warps of 64x64 (gemm2) / 64x32-per-matrix
// (gemm1), __launch_bounds__(128, 2) -> 2 CTAs/SM with 256 regs/thread.
// ============================================================================

// ============================================================================
// GEMM1: block 128(M) x 64(N), 128 thr, warps 2x2, fused gate+up.
// ============================================================================
__global__ void __launch_bounds__(128, 2) gemm1_kernel(
    const float* __restrict__ x,
    const float* __restrict__ w_gate,
    const float* __restrict__ w_up)
{
    int e = blockIdx.z;
    int cnt = g_cnt[e];
    int row0 = blockIdx.y * 128;
    if (row0 >= cnt) return;
    int col0 = blockIdx.x * 64;
    const float* Bg = w_gate + (size_t)e * Hd * Ff + col0;
    const float* Bu = w_up   + (size_t)e * Hd * Ff + col0;

    __shared__ __align__(16) float sA[2][128 * 16];
    __shared__ __align__(16) float sG[2][16 * 72];
    __shared__ __align__(16) float sU[2][16 * 72];

    int t = threadIdx.x, lane = t & 31, warp = t >> 5;
    int wm = warp >> 1, wn = warp & 1;
    int qr = lane >> 2, qc = lane & 3;
    int sfr = 4 * (qc ^ ((qr >> 1) & 3));   // A-fragment word slot (mt-invariant)

    // A fetch: c = t&3, rows r0+32j (j<4)
    int c = t & 3, r0 = t >> 2;
    int pr = (r0 >> 1) & 3;
    const float* ap[4];
#pragma unroll
    for (int j = 0; j < 4; j++) {
        int r = row0 + r0 + 32 * j;
        ap[j] = (r < cnt) ? (x + (size_t)g_tok[e][r] * Hd + 4 * c) : nullptr;
    }
    // B fetch: n4 = t&15, kb = t>>4 (0..7), rows kb+8j (j<2)
    int n4 = t & 15, kb = t >> 4;
    const float* bg = Bg + 4 * n4;
    const float* bu = Bu + 4 * n4;

    float accG[4][4][4], accU[4][4][4];
#pragma unroll
    for (int a = 0; a < 4; a++)
#pragma unroll
        for (int b = 0; b < 4; b++)
#pragma unroll
            for (int d = 0; d < 4; d++) { accG[a][b][d] = 0.f; accU[a][b][d] = 0.f; }

    float4 la[4], lg[2], lu[2];
    auto fetch = [&](int k0) {
#pragma unroll
        for (int j = 0; j < 4; j++)
            la[j] = ap[j] ? *(const float4*)(ap[j] + k0) : make_float4(0, 0, 0, 0);
#pragma unroll
        for (int j = 0; j < 2; j++) {
            lg[j] = *(const float4*)(bg + (size_t)(k0 + kb + 8 * j) * Ff);
            lu[j] = *(const float4*)(bu + (size_t)(k0 + kb + 8 * j) * Ff);
        }
    };
    auto stage = [&](int buf) {
#pragma unroll
        for (int j = 0; j < 4; j++) {
            float* rowp = &sA[buf][(r0 + 32 * j) * 16 + c];
            rowp[4 * (0 ^ pr)] = f2tf(la[j].x);
            rowp[4 * (1 ^ pr)] = f2tf(la[j].y);
            rowp[4 * (2 ^ pr)] = f2tf(la[j].z);
            rowp[4 * (3 ^ pr)] = f2tf(la[j].w);
        }
#pragma unroll
        for (int j = 0; j < 2; j++) {
            *(float4*)&sG[buf][(kb + 8 * j) * 72 + 4 * n4] =
                make_float4(f2tf(lg[j].x), f2tf(lg[j].y), f2tf(lg[j].z), f2tf(lg[j].w));
            *(float4*)&sU[buf][(kb + 8 * j) * 72 + 4 * n4] =
                make_float4(f2tf(lu[j].x), f2tf(lu[j].y), f2tf(lu[j].z), f2tf(lu[j].w));
        }
    };

    fetch(0); stage(0);
    __syncthreads();
    const int KT = Hd / 16;   // 64
    for (int kt = 0; kt < KT; kt++) {
        int buf = kt & 1;
        if (kt + 1 < KT) fetch((kt + 1) * 16);

        // all A fragments (64 M rows)
        float4 alo[4], ahi[4];
#pragma unroll
        for (int mt = 0; mt < 4; mt++) {
            int R = wm * 64 + mt * 16 + qr;
            alo[mt] = *(const float4*)&sA[buf][R * 16 + sfr];
            ahi[mt] = *(const float4*)&sA[buf][(R + 8) * 16 + sfr];
        }
        // N in halves (2 nt at a time) for both matrices
#pragma unroll
        for (int nth = 0; nth < 2; nth++) {
            unsigned bgf[2][2][2], buf2[2][2][2];
#pragma unroll
            for (int nt2 = 0; nt2 < 2; nt2++) {
                int n = wn * 32 + (nth * 2 + nt2) * 8 + qr;
#pragma unroll
                for (int ks = 0; ks < 2; ks++) {
                    bgf[nt2][ks][0] = __float_as_uint(sG[buf][(ks * 8 + qc) * 72 + n]);
                    bgf[nt2][ks][1] = __float_as_uint(sG[buf][(ks * 8 + qc + 4) * 72 + n]);
                    buf2[nt2][ks][0] = __float_as_uint(sU[buf][(ks * 8 + qc) * 72 + n]);
                    buf2[nt2][ks][1] = __float_as_uint(sU[buf][(ks * 8 + qc + 4) * 72 + n]);
                }
            }
#pragma unroll
            for (int nt2 = 0; nt2 < 2; nt2++)
#pragma unroll
                for (int ks = 0; ks < 2; ks++)
#pragma unroll
                    for (int mt = 0; mt < 4; mt++) {
                        const float* al = (const float*)&alo[mt];
                        const float* ah = (const float*)&ahi[mt];
                        unsigned af[4] = { __float_as_uint(al[2 * ks]), __float_as_uint(ah[2 * ks]),
                                           __float_as_uint(al[2 * ks + 1]), __float_as_uint(ah[2 * ks + 1]) };
                        mma8(accG[mt][nth * 2 + nt2], af, bgf[nt2][ks]);
                        mma8(accU[mt][nth * 2 + nt2], af, buf2[nt2][ks]);
                    }
        }
        if (kt + 1 < KT) stage(buf ^ 1);
        __syncthreads();
    }

    // epilogue: h = silu(g) * u -> g_h[tok*2+slot]
#pragma unroll
    for (int mt = 0; mt < 4; mt++) {
#pragma unroll
        for (int half = 0; half < 2; half++) {
            int r = row0 + wm * 64 + mt * 16 + qr + half * 8;
            if (r < cnt) {
                int aid = g_tok[e][r] * 2 + g_slot[e][r];
                float* hrow = g_h + (size_t)aid * Ff + col0;
#pragma unroll
                for (int nt = 0; nt < 4; nt++) {
                    float gg0 = accG[mt][nt][half * 2 + 0], gg1 = accG[mt][nt][half * 2 + 1];
                    float uu0 = accU[mt][nt][half * 2 + 0], uu1 = accU[mt][nt][half * 2 + 1];
                    float h0 = gg0 * uu0 / (1.f + __expf(-gg0));
                    float h1 = gg1 * uu1 / (1.f + __expf(-gg1));
                    int cc = wn * 32 + nt * 8 + 2 * qc;
                    *(float2*)(hrow + cc) = make_float2(h0, h1);
                }
            }
        }
    }
}

// ============================================================================
// GEMM2: block 128(M) x 128(N), 128 thr, warps 2x2 (tile 64x64)
// ============================================================================
__global__ void __launch_bounds__(128, 2) gemm2_kernel(const float* __restrict__ w_down)
{
    int e = blockIdx.z;
    int cnt = g_cnt[e];
    int row0 = blockIdx.y * 128;
    if (row0 >= cnt) return;
    int col0 = blockIdx.x * 128;
    const float* Bd = w_down + (size_t)e * Ff * Hd + col0;

    __shared__ __align__(16) float sA[2][128 * 16];
    __shared__ __align__(16) float sB[2][16 * 136];

    int t = threadIdx.x, lane = t & 31, warp = t >> 5;
    int wm = warp >> 1, wn = warp & 1;
    int qr = lane >> 2, qc = lane & 3;
    int sfr = 4 * (qc ^ ((qr >> 1) & 3));

    int c = t & 3, r0 = t >> 2;
    int pr = (r0 >> 1) & 3;
    const float* ap[4];
#pragma unroll
    for (int j = 0; j < 4; j++) {
        int r = row0 + r0 + 32 * j;
        if (r < cnt) {
            int aid = g_tok[e][r] * 2 + g_slot[e][r];
            ap[j] = g_h + (size_t)aid * Ff + 4 * c;
        } else ap[j] = nullptr;
    }
    // B fetch: n4 = lane, kb = warp (0..3), rows kb+4j (j<4)
    int n4 = lane, kb = warp;
    const float* bp = Bd + 4 * n4;

    float acc[4][8][4];
#pragma unroll
    for (int a = 0; a < 4; a++)
#pragma unroll
        for (int b = 0; b < 8; b++)
#pragma unroll
            for (int d = 0; d < 4; d++) acc[a][b][d] = 0.f;

    float4 la[4], lb[4];
    auto fetch = [&](int k0) {
#pragma unroll
        for (int j = 0; j < 4; j++)
            la[j] = ap[j] ? *(const float4*)(ap[j] + k0) : make_float4(0, 0, 0, 0);
#pragma unroll
        for (int j = 0; j < 4; j++)
            lb[j] = *(const float4*)(bp + (size_t)(k0 + kb + 4 * j) * Hd);
    };
    auto stage = [&](int buf) {
#pragma unroll
        for (int j = 0; j < 4; j++) {
            float* rowp = &sA[buf][(r0 + 32 * j) * 16 + c];
            rowp[4 * (0 ^ pr)] = f2tf(la[j].x);
            rowp[4 * (1 ^ pr)] = f2tf(la[j].y);
            rowp[4 * (2 ^ pr)] = f2tf(la[j].z);
            rowp[4 * (3 ^ pr)] = f2tf(la[j].w);
        }
#pragma unroll
        for (int j = 0; j < 4; j++)
            *(float4*)&sB[buf][(kb + 4 * j) * 136 + 4 * n4] =
                make_float4(f2tf(lb[j].x), f2tf(lb[j].y), f2tf(lb[j].z), f2tf(lb[j].w));
    };

    fetch(0); stage(0);
    __syncthreads();
    const int KT = Ff / 16;   // 256
    for (int kt = 0; kt < KT; kt++) {
        int buf = kt & 1;
        if (kt + 1 < KT) fetch((kt + 1) * 16);

        float4 alo[4], ahi[4];
#pragma unroll
        for (int mt = 0; mt < 4; mt++) {
            int R = wm * 64 + mt * 16 + qr;
            alo[mt] = *(const float4*)&sA[buf][R * 16 + sfr];
            ahi[mt] = *(const float4*)&sA[buf][(R + 8) * 16 + sfr];
        }
#pragma unroll
        for (int nth = 0; nth < 2; nth++) {
            unsigned bf[4][2][2];
#pragma unroll
            for (int nt2 = 0; nt2 < 4; nt2++) {
                int n = wn * 64 + (nth * 4 + nt2) * 8 + qr;
#pragma unroll
                for (int ks = 0; ks < 2; ks++) {
                    bf[nt2][ks][0] = __float_as_uint(sB[buf][(ks * 8 + qc) * 136 + n]);
                    bf[nt2][ks][1] = __float_as_uint(sB[buf][(ks * 8 + qc + 4) * 136 + n]);
                }
            }
#pragma unroll
            for (int nt2 = 0; nt2 < 4; nt2++)
#pragma unroll
                for (int ks = 0; ks < 2; ks++)
#pragma unroll
                    for (int mt = 0; mt < 4; mt++) {
                        const float* al = (const float*)&alo[mt];
                        const float* ah = (const float*)&ahi[mt];
                        unsigned af[4] = { __float_as_uint(al[2 * ks]), __float_as_uint(ah[2 * ks]),
                                           __float_as_uint(al[2 * ks + 1]), __float_as_uint(ah[2 * ks + 1]) };
                        mma8(acc[mt][nth * 4 + nt2], af, bf[nt2][ks]);
                    }
        }
        if (kt + 1 < KT) stage(buf ^ 1);
        __syncthreads();
    }

#pragma unroll
    for (int mt = 0; mt < 4; mt++) {
#pragma unroll
        for (int half = 0; half < 2; half++) {
            int r = row0 + wm * 64 + mt * 16 + qr + half * 8;
            if (r < cnt) {
                int tok = g_tok[e][r];
                float w = g_wt[e][r];
                int sl  = g_slot[e][r];
                float* orow = g_sbuf + (size_t)sl * NT * Hd + (size_t)tok * Hd + col0;
#pragma unroll
                for (int nt = 0; nt < 8; nt++) {
                    int cc = wn * 64 + nt * 8 + 2 * qc;
                    *(float2*)(orow + cc) = make_float2(w * acc[mt][nt][half * 2 + 0],
                                                        w * acc[mt][nt][half * 2 + 1]);
                }
            }
        }
    }
}

__global__ void combine_kernel(float* __restrict__ out) {
    int i = blockIdx.x * 256 + threadIdx.x;
    if (i < NT * Hd / 4) {
        float4 a = ((const float4*)g_sbuf)[i];
        float4 b = ((const float4*)(g_sbuf + NT * Hd))[i];
        ((float4*)out)[i] = make_float4(a.x + b.x, a.y + b.y, a.z + b.z, a.w + b.w);
    }
}

// ---------------- launch ----------------
extern "C" void kernel_launch(void* const* d_in, const int* in_sizes, int n_in,
                              void* d_out, int out_size) {
    (void)in_sizes; (void)n_in; (void)out_size;
    const float* x      = (const float*)d_in[0];
    const float* gw     = (const float*)d_in[1];
    const float* w_gate = (const float*)d_in[2];
    const float* w_up   = (const float*)d_in[3];
    const float* w_down = (const float*)d_in[4];
    float* out = (float*)d_out;

    zero_kernel<<<1, 32>>>();
    router_kernel<<<NT / 8, 256>>>(x, gw);
    gemm1_kernel<<<dim3(Ff / 64, NT / 128, NE), 128>>>(x, w_gate, w_up);
    gemm2_kernel<<<dim3(Hd / 128, NT / 128, NE), 128>>>(w_down);
    combine_kernel<<<(NT * Hd / 4 + 255) / 256, 256>>>(out);
}

// round 13
// speedup vs baseline: 1.0121x; 1.0121x over previous
#include <cuda_runtime.h>
#include <cstdint>

// Problem constants
constexpr int Hd = 1024;   // hidden
constexpr int Ff = 4096;   // intermediate
constexpr int NE = 8;      // experts
constexpr int NT = 2048;   // tokens
constexpr int NA = 2 * NT; // assignments (top-2)

// ---------------- device scratch (no allocations allowed) ----------------
__device__ int   g_cnt[NE];
__device__ int   g_tok[NE][NT];
__device__ float g_wt[NE][NT];
__device__ int   g_slot[NE][NT];
__device__ float g_xt[(size_t)NT * Hd];  // x, tf32-rounded + k-interleaved (8 MB)
__device__ float g_h[(size_t)NA * Ff];   // intermediate, tf32-rounded + k-interleaved (64 MB)
__device__ float g_sbuf[2 * NT * Hd];    // per-rank-slot output buffers

// ---------------- helpers ----------------
__device__ __forceinline__ float f2tf(float x) {
    unsigned u;
    asm("cvt.rna.tf32.f32 %0, %1;" : "=r"(u) : "f"(x));
    return __uint_as_float(u);
}
__device__ __forceinline__ void mma8(float c[4], const unsigned a[4], const unsigned b[2]) {
    asm volatile(
        "mma.sync.aligned.m16n8k8.row.col.f32.tf32.tf32.f32 "
        "{%0,%1,%2,%3},{%4,%5,%6,%7},{%8,%9},{%0,%1,%2,%3};"
        : "+f"(c[0]), "+f"(c[1]), "+f"(c[2]), "+f"(c[3])
        : "r"(a[0]), "r"(a[1]), "r"(a[2]), "r"(a[3]), "r"(b[0]), "r"(b[1]));
}

// ---------------- small kernels ----------------
__global__ void zero_kernel() {
    if (threadIdx.x < NE) g_cnt[threadIdx.x] = 0;
}

// x -> g_xt: tf32 round + k-interleave (word = 4*(k%4)+k/4 within each 16-k group)
__global__ void xprep_kernel(const float* __restrict__ x) {
    int idx = blockIdx.x * 256 + threadIdx.x;
    if (idx < NT * Hd) {
        int row = idx >> 10, k = idx & 1023;
        int w = (k & ~15) + 4 * (k & 3) + ((k & 15) >> 2);
        g_xt[(size_t)row * Hd + w] = f2tf(x[idx]);
    }
}

// One warp per token: logits -> softmax -> top-2 -> softmax of the two PROBS.
__global__ void router_kernel(const float* __restrict__ x, const float* __restrict__ gw) {
    int tok  = blockIdx.x * 8 + (threadIdx.x >> 5);
    int lane = threadIdx.x & 31;
    if (tok >= NT) return;
    const float* xr = x + (size_t)tok * Hd;

    float acc[NE];
#pragma unroll
    for (int e = 0; e < NE; e++) acc[e] = 0.f;
    for (int i = lane; i < Hd; i += 32) {
        float xv = xr[i];
        const float* g = gw + i * NE;
#pragma unroll
        for (int e = 0; e < NE; e++) acc[e] = fmaf(xv, g[e], acc[e]);
    }
#pragma unroll
    for (int e = 0; e < NE; e++) {
#pragma unroll
        for (int o = 16; o > 0; o >>= 1) acc[e] += __shfl_xor_sync(0xffffffffu, acc[e], o);
    }
    if (lane == 0) {
        float m = acc[0];
#pragma unroll
        for (int e = 1; e < NE; e++) m = fmaxf(m, acc[e]);
        float p[NE], s = 0.f;
#pragma unroll
        for (int e = 0; e < NE; e++) { p[e] = expf(acc[e] - m); s += p[e]; }
        float inv = 1.f / s;
#pragma unroll
        for (int e = 0; e < NE; e++) p[e] *= inv;

        int i0 = 0;
#pragma unroll
        for (int e = 1; e < NE; e++) if (p[e] > p[i0]) i0 = e;
        int i1 = (i0 == 0) ? 1 : 0;
#pragma unroll
        for (int e = 0; e < NE; e++) if (e != i0 && p[e] > p[i1]) i1 = e;

        float eb = expf(p[i1] - p[i0]);       // <= 1
        float w0 = 1.f / (1.f + eb);
        float w1 = 1.f - w0;

        int s0 = atomicAdd(&g_cnt[i0], 1);
        g_tok[i0][s0] = tok; g_wt[i0][s0] = w0; g_slot[i0][s0] = 0;
        int s1 = atomicAdd(&g_cnt[i1], 1);
        g_tok[i1][s1] = tok; g_wt[i1][s1] = w1; g_slot[i1][s1] = 1;
    }
}

// ============================================================================
// Layouts:
//  A smem: [128 rows][16 words], SOURCE already k-interleaved -> identity
//          LDG.128 -> STS.128 staging, no cvt. Fragment: LDS.128 at word 4*qc
//          yields k = qc, qc+4, qc+8, qc+12 (both k8 steps).
//  B smem: [16 k-rows][pitch], pitch 136 (N=128) / 72 (N=64); STS.128 staging
//          with cvt; scalar LDS.32 fragments (conflict-free).
// ============================================================================

// ============================================================================
// GEMM1: block 128(M) x 64(N), 128 thr, warps 2x2, fused gate+up.
// ============================================================================
__global__ void __launch_bounds__(128, 2) gemm1_kernel(
    const float* __restrict__ w_gate,
    const float* __restrict__ w_up)
{
    int e = blockIdx.z;
    int cnt = g_cnt[e];
    int row0 = blockIdx.y * 128;
    if (row0 >= cnt) return;
    int col0 = blockIdx.x * 64;
    const float* Bg = w_gate + (size_t)e * Hd * Ff + col0;
    const float* Bu = w_up   + (size_t)e * Hd * Ff + col0;

    __shared__ __align__(16) float sA[2][128 * 16];
    __shared__ __align__(16) float sG[2][16 * 72];
    __shared__ __align__(16) float sU[2][16 * 72];

    int t = threadIdx.x, lane = t & 31, warp = t >> 5;
    int wm = warp >> 1, wn = warp & 1;
    int qr = lane >> 2, qc = lane & 3;
    int sfr = 4 * qc;   // A-fragment word slot (identity layout)

    // A fetch: c = t&3 (16B chunk), rows r0+32j (j<4)
    int c = t & 3, r0 = t >> 2;
    const float* ap[4];
#pragma unroll
    for (int j = 0; j < 4; j++) {
        int r = row0 + r0 + 32 * j;
        ap[j] = (r < cnt) ? (g_xt + (size_t)g_tok[e][r] * Hd + 4 * c) : nullptr;
    }
    // B fetch: n4 = t&15, kb = t>>4 (0..7), rows kb+8j (j<2)
    int n4 = t & 15, kb = t >> 4;
    const float* bg = Bg + 4 * n4;
    const float* bu = Bu + 4 * n4;

    float accG[4][4][4], accU[4][4][4];
#pragma unroll
    for (int a = 0; a < 4; a++)
#pragma unroll
        for (int b = 0; b < 4; b++)
#pragma unroll
            for (int d = 0; d < 4; d++) { accG[a][b][d] = 0.f; accU[a][b][d] = 0.f; }

    float4 la[4], lg[2], lu[2];
    auto fetch = [&](int k0) {
#pragma unroll
        for (int j = 0; j < 4; j++)
            la[j] = ap[j] ? *(const float4*)(ap[j] + k0) : make_float4(0, 0, 0, 0);
#pragma unroll
        for (int j = 0; j < 2; j++) {
            lg[j] = *(const float4*)(bg + (size_t)(k0 + kb + 8 * j) * Ff);
            lu[j] = *(const float4*)(bu + (size_t)(k0 + kb + 8 * j) * Ff);
        }
    };
    auto stage = [&](int buf) {
#pragma unroll
        for (int j = 0; j < 4; j++)
            *(float4*)&sA[buf][(r0 + 32 * j) * 16 + 4 * c] = la[j];   // identity copy
#pragma unroll
        for (int j = 0; j < 2; j++) {
            *(float4*)&sG[buf][(kb + 8 * j) * 72 + 4 * n4] =
                make_float4(f2tf(lg[j].x), f2tf(lg[j].y), f2tf(lg[j].z), f2tf(lg[j].w));
            *(float4*)&sU[buf][(kb + 8 * j) * 72 + 4 * n4] =
                make_float4(f2tf(lu[j].x), f2tf(lu[j].y), f2tf(lu[j].z), f2tf(lu[j].w));
        }
    };

    fetch(0); stage(0);
    __syncthreads();
    const int KT = Hd / 16;   // 64
    for (int kt = 0; kt < KT; kt++) {
        int buf = kt & 1;
        if (kt + 1 < KT) fetch((kt + 1) * 16);

        float4 alo[4], ahi[4];
#pragma unroll
        for (int mt = 0; mt < 4; mt++) {
            int R = wm * 64 + mt * 16 + qr;
            alo[mt] = *(const float4*)&sA[buf][R * 16 + sfr];
            ahi[mt] = *(const float4*)&sA[buf][(R + 8) * 16 + sfr];
        }
#pragma unroll
        for (int nth = 0; nth < 2; nth++) {
            unsigned bgf[2][2][2], buf2[2][2][2];
#pragma unroll
            for (int nt2 = 0; nt2 < 2; nt2++) {
                int n = wn * 32 + (nth * 2 + nt2) * 8 + qr;
#pragma unroll
                for (int ks = 0; ks < 2; ks++) {
                    bgf[nt2][ks][0] = __float_as_uint(sG[buf][(ks * 8 + qc) * 72 + n]);
                    bgf[nt2][ks][1] = __float_as_uint(sG[buf][(ks * 8 + qc + 4) * 72 + n]);
                    buf2[nt2][ks][0] = __float_as_uint(sU[buf][(ks * 8 + qc) * 72 + n]);
                    buf2[nt2][ks][1] = __float_as_uint(sU[buf][(ks * 8 + qc + 4) * 72 + n]);
                }
            }
#pragma unroll
            for (int nt2 = 0; nt2 < 2; nt2++)
#pragma unroll
                for (int ks = 0; ks < 2; ks++)
#pragma unroll
                    for (int mt = 0; mt < 4; mt++) {
                        const float* al = (const float*)&alo[mt];
                        const float* ah = (const float*)&ahi[mt];
                        unsigned af[4] = { __float_as_uint(al[2 * ks]), __float_as_uint(ah[2 * ks]),
                                           __float_as_uint(al[2 * ks + 1]), __float_as_uint(ah[2 * ks + 1]) };
                        mma8(accG[mt][nth * 2 + nt2], af, bgf[nt2][ks]);
                        mma8(accU[mt][nth * 2 + nt2], af, buf2[nt2][ks]);
                    }
        }
        if (kt + 1 < KT) stage(buf ^ 1);
        __syncthreads();
    }

    // epilogue: h = silu(g) * u -> g_h[tok*2+slot], tf32-rounded + k-interleaved
#pragma unroll
    for (int mt = 0; mt < 4; mt++) {
#pragma unroll
        for (int half = 0; half < 2; half++) {
            int r = row0 + wm * 64 + mt * 16 + qr + half * 8;
            if (r < cnt) {
                int aid = g_tok[e][r] * 2 + g_slot[e][r];
                float* hrow = g_h + (size_t)aid * Ff + col0;
#pragma unroll
                for (int nt = 0; nt < 4; nt++) {
                    float gg0 = accG[mt][nt][half * 2 + 0], gg1 = accG[mt][nt][half * 2 + 1];
                    float uu0 = accU[mt][nt][half * 2 + 0], uu1 = accU[mt][nt][half * 2 + 1];
                    float h0 = gg0 * uu0 / (1.f + __expf(-gg0));
                    float h1 = gg1 * uu1 / (1.f + __expf(-gg1));
                    int cc = wn * 32 + nt * 8 + 2 * qc;          // even
                    int i0 = cc & 15;
                    int w0 = (cc & ~15) + 4 * (i0 & 3) + (i0 >> 2);
                    hrow[w0]     = f2tf(h0);                     // i0
                    hrow[w0 + 4] = f2tf(h1);                     // i0+1
                }
            }
        }
    }
}

// ============================================================================
// GEMM2: block 128(M) x 128(N), 128 thr, warps 2x2 (tile 64x64)
// ============================================================================
__global__ void __launch_bounds__(128, 2) gemm2_kernel(const float* __restrict__ w_down)
{
    int e = blockIdx.z;
    int cnt = g_cnt[e];
    int row0 = blockIdx.y * 128;
    if (row0 >= cnt) return;
    int col0 = blockIdx.x * 128;
    const float* Bd = w_down + (size_t)e * Ff * Hd + col0;

    __shared__ __align__(16) float sA[2][128 * 16];
    __shared__ __align__(16) float sB[2][16 * 136];

    int t = threadIdx.x, lane = t & 31, warp = t >> 5;
    int wm = warp >> 1, wn = warp & 1;
    int qr = lane >> 2, qc = lane & 3;
    int sfr = 4 * qc;

    int c = t & 3, r0 = t >> 2;
    const float* ap[4];
#pragma unroll
    for (int j = 0; j < 4; j++) {
        int r = row0 + r0 + 32 * j;
        if (r < cnt) {
            int aid = g_tok[e][r] * 2 + g_slot[e][r];
            ap[j] = g_h + (size_t)aid * Ff + 4 * c;
        } else ap[j] = nullptr;
    }
    int n4 = lane, kb = warp;
    const float* bp = Bd + 4 * n4;

    float acc[4][8][4];
#pragma unroll
    for (int a = 0; a < 4; a++)
#pragma unroll
        for (int b = 0; b < 8; b++)
#pragma unroll
            for (int d = 0; d < 4; d++) acc[a][b][d] = 0.f;

    float4 la[4], lb[4];
    auto fetch = [&](int k0) {
#pragma unroll
        for (int j = 0; j < 4; j++)
            la[j] = ap[j] ? *(const float4*)(ap[j] + k0) : make_float4(0, 0, 0, 0);
#pragma unroll
        for (int j = 0; j < 4; j++)
            lb[j] = *(const float4*)(bp + (size_t)(k0 + kb + 4 * j) * Hd);
    };
    auto stage = [&](int buf) {
#pragma unroll
        for (int j = 0; j < 4; j++)
            *(float4*)&sA[buf][(r0 + 32 * j) * 16 + 4 * c] = la[j];   // identity copy
#pragma unroll
        for (int j = 0; j < 4; j++)
            *(float4*)&sB[buf][(kb + 4 * j) * 136 + 4 * n4] =
                make_float4(f2tf(lb[j].x), f2tf(lb[j].y), f2tf(lb[j].z), f2tf(lb[j].w));
    };

    fetch(0); stage(0);
    __syncthreads();
    const int KT = Ff / 16;   // 256
    for (int kt = 0; kt < KT; kt++) {
        int buf = kt & 1;
        if (kt + 1 < KT) fetch((kt + 1) * 16);

        float4 alo[4], ahi[4];
#pragma unroll
        for (int mt = 0; mt < 4; mt++) {
            int R = wm * 64 + mt * 16 + qr;
            alo[mt] = *(const float4*)&sA[buf][R * 16 + sfr];
            ahi[mt] = *(const float4*)&sA[buf][(R + 8) * 16 + sfr];
        }
#pragma unroll
        for (int nth = 0; nth < 2; nth++) {
            unsigned bf[4][2][2];
#pragma unroll
            for (int nt2 = 0; nt2 < 4; nt2++) {
                int n = wn * 64 + (nth * 4 + nt2) * 8 + qr;
#pragma unroll
                for (int ks = 0; ks < 2; ks++) {
                    bf[nt2][ks][0] = __float_as_uint(sB[buf][(ks * 8 + qc) * 136 + n]);
                    bf[nt2][ks][1] = __float_as_uint(sB[buf][(ks * 8 + qc + 4) * 136 + n]);
                }
            }
#pragma unroll
            for (int nt2 = 0; nt2 < 4; nt2++)
#pragma unroll
                for (int ks = 0; ks < 2; ks++)
#pragma unroll
                    for (int mt = 0; mt < 4; mt++) {
                        const float* al = (const float*)&alo[mt];
                        const float* ah = (const float*)&ahi[mt];
                        unsigned af[4] = { __float_as_uint(al[2 * ks]), __float_as_uint(ah[2 * ks]),
                                           __float_as_uint(al[2 * ks + 1]), __float_as_uint(ah[2 * ks + 1]) };
                        mma8(acc[mt][nth * 4 + nt2], af, bf[nt2][ks]);
                    }
        }
        if (kt + 1 < KT) stage(buf ^ 1);
        __syncthreads();
    }

#pragma unroll
    for (int mt = 0; mt < 4; mt++) {
#pragma unroll
        for (int half = 0; half < 2; half++) {
            int r = row0 + wm * 64 + mt * 16 + qr + half * 8;
            if (r < cnt) {
                int tok = g_tok[e][r];
                float w = g_wt[e][r];
                int sl  = g_slot[e][r];
                float* orow = g_sbuf + (size_t)sl * NT * Hd + (size_t)tok * Hd + col0;
#pragma unroll
                for (int nt = 0; nt < 8; nt++) {
                    int cc = wn * 64 + nt * 8 + 2 * qc;
                    *(float2*)(orow + cc) = make_float2(w * acc[mt][nt][half * 2 + 0],
                                                        w * acc[mt][nt][half * 2 + 1]);
                }
            }
        }
    }
}

__global__ void combine_kernel(float* __restrict__ out) {
    int i = blockIdx.x * 256 + threadIdx.x;
    if (i < NT * Hd / 4) {
        float4 a = ((const float4*)g_sbuf)[i];
        float4 b = ((const float4*)(g_sbuf + NT * Hd))[i];
        ((float4*)out)[i] = make_float4(a.x + b.x, a.y + b.y, a.z + b.z, a.w + b.w);
    }
}

// ---------------- launch ----------------
extern "C" void kernel_launch(void* const* d_in, const int* in_sizes, int n_in,
                              void* d_out, int out_size) {
    (void)in_sizes; (void)n_in; (void)out_size;
    const float* x      = (const float*)d_in[0];
    const float* gw     = (const float*)d_in[1];
    const float* w_gate = (const float*)d_in[2];
    const float* w_up   = (const float*)d_in[3];
    const float* w_down = (const float*)d_in[4];
    float* out = (float*)d_out;

    zero_kernel<<<1, 32>>>();
    xprep_kernel<<<(NT * Hd) / 256, 256>>>(x);
    router_kernel<<<NT / 8, 256>>>(x, gw);
    gemm1_kernel<<<dim3(Ff / 64, NT / 128, NE), 128>>>(w_gate, w_up);
    gemm2_kernel<<<dim3(Hd / 128, NT / 128, NE), 128>>>(w_down);
    combine_kernel<<<(NT * Hd / 4 + 255) / 256, 256>>>(out);
}

// round 14
// speedup vs baseline: 1.0140x; 1.0019x over previous
#include <cuda_runtime.h>
#include <cstdint>

// Problem constants
constexpr int Hd = 1024;   // hidden
constexpr int Ff = 4096;   // intermediate
constexpr int NE = 8;      // experts
constexpr int NT = 2048;   // tokens
constexpr int NA = 2 * NT; // assignments (top-2)

// ---------------- device scratch (no allocations allowed) ----------------
__device__ int   g_cnt[NE];
__device__ int   g_tok[NE][NT];
__device__ float g_wt[NE][NT];
__device__ int   g_slot[NE][NT];
__device__ float g_xt[(size_t)NT * Hd];  // x, tf32-rounded + k-interleaved (8 MB)
__device__ float g_h[(size_t)NA * Ff];   // intermediate, tf32-rounded + k-interleaved (64 MB)
__device__ float g_sbuf[2 * NT * Hd];    // per-rank-slot output buffers

// ---------------- helpers ----------------
__device__ __forceinline__ float f2tf(float x) {
    unsigned u;
    asm("cvt.rna.tf32.f32 %0, %1;" : "=r"(u) : "f"(x));
    return __uint_as_float(u);
}
// Scalar-operand HMMA: operands map straight to registers, no array marshalling.
__device__ __forceinline__ void mma8(float c[4],
                                     unsigned a0, unsigned a1, unsigned a2, unsigned a3,
                                     unsigned b0, unsigned b1) {
    asm volatile(
        "mma.sync.aligned.m16n8k8.row.col.f32.tf32.tf32.f32 "
        "{%0,%1,%2,%3},{%4,%5,%6,%7},{%8,%9},{%0,%1,%2,%3};"
        : "+f"(c[0]), "+f"(c[1]), "+f"(c[2]), "+f"(c[3])
        : "r"(a0), "r"(a1), "r"(a2), "r"(a3), "r"(b0), "r"(b1));
}

// ---------------- small kernels ----------------
__global__ void zero_kernel() {
    if (threadIdx.x < NE) g_cnt[threadIdx.x] = 0;
}

// x -> g_xt: tf32 round + k-interleave (word = 4*(k%4)+k/4 within each 16-k group)
__global__ void xprep_kernel(const float* __restrict__ x) {
    int idx = blockIdx.x * 256 + threadIdx.x;
    if (idx < NT * Hd) {
        int row = idx >> 10, k = idx & 1023;
        int w = (k & ~15) + 4 * (k & 3) + ((k & 15) >> 2);
        g_xt[(size_t)row * Hd + w] = f2tf(x[idx]);
    }
}

// One warp per token: logits -> softmax -> top-2 -> softmax of the two PROBS.
__global__ void router_kernel(const float* __restrict__ x, const float* __restrict__ gw) {
    int tok  = blockIdx.x * 8 + (threadIdx.x >> 5);
    int lane = threadIdx.x & 31;
    if (tok >= NT) return;
    const float* xr = x + (size_t)tok * Hd;

    float acc[NE];
#pragma unroll
    for (int e = 0; e < NE; e++) acc[e] = 0.f;
    for (int i = lane; i < Hd; i += 32) {
        float xv = xr[i];
        const float* g = gw + i * NE;
#pragma unroll
        for (int e = 0; e < NE; e++) acc[e] = fmaf(xv, g[e], acc[e]);
    }
#pragma unroll
    for (int e = 0; e < NE; e++) {
#pragma unroll
        for (int o = 16; o > 0; o >>= 1) acc[e] += __shfl_xor_sync(0xffffffffu, acc[e], o);
    }
    if (lane == 0) {
        float m = acc[0];
#pragma unroll
        for (int e = 1; e < NE; e++) m = fmaxf(m, acc[e]);
        float p[NE], s = 0.f;
#pragma unroll
        for (int e = 0; e < NE; e++) { p[e] = expf(acc[e] - m); s += p[e]; }
        float inv = 1.f / s;
#pragma unroll
        for (int e = 0; e < NE; e++) p[e] *= inv;

        int i0 = 0;
#pragma unroll
        for (int e = 1; e < NE; e++) if (p[e] > p[i0]) i0 = e;
        int i1 = (i0 == 0) ? 1 : 0;
#pragma unroll
        for (int e = 0; e < NE; e++) if (e != i0 && p[e] > p[i1]) i1 = e;

        float eb = expf(p[i1] - p[i0]);       // <= 1
        float w0 = 1.f / (1.f + eb);
        float w1 = 1.f - w0;

        int s0 = atomicAdd(&g_cnt[i0], 1);
        g_tok[i0][s0] = tok; g_wt[i0][s0] = w0; g_slot[i0][s0] = 0;
        int s1 = atomicAdd(&g_cnt[i1], 1);
        g_tok[i1][s1] = tok; g_wt[i1][s1] = w1; g_slot[i1][s1] = 1;
    }
}

// ============================================================================
// Layouts (identical to R13):
//  A smem: [128 rows][16 words], source pre-interleaved -> identity LDG.128 ->
//          STS.128 staging. Fragment: one LDS.128 at word 4*qc gives
//          k = qc, qc+4 (ks=0: .x/.y) and qc+8, qc+12 (ks=1: .z/.w).
//  B smem: [16 k-rows][pitch 136/72]; STS.128 staging with cvt; scalar LDS.32
//          fragments, conflict-free.
// ============================================================================

// ============================================================================
// GEMM1: block 128(M) x 64(N), 128 thr, warps 2x2, fused gate+up.
// ============================================================================
__global__ void __launch_bounds__(128, 2) gemm1_kernel(
    const float* __restrict__ w_gate,
    const float* __restrict__ w_up)
{
    int e = blockIdx.z;
    int cnt = g_cnt[e];
    int row0 = blockIdx.y * 128;
    if (row0 >= cnt) return;
    int col0 = blockIdx.x * 64;
    const float* Bg = w_gate + (size_t)e * Hd * Ff + col0;
    const float* Bu = w_up   + (size_t)e * Hd * Ff + col0;

    __shared__ __align__(16) float sA[2][128 * 16];
    __shared__ __align__(16) float sG[2][16 * 72];
    __shared__ __align__(16) float sU[2][16 * 72];

    int t = threadIdx.x, lane = t & 31, warp = t >> 5;
    int wm = warp >> 1, wn = warp & 1;
    int qr = lane >> 2, qc = lane & 3;
    int sfr = 4 * qc;

    int c = t & 3, r0 = t >> 2;
    const float* ap[4];
#pragma unroll
    for (int j = 0; j < 4; j++) {
        int r = row0 + r0 + 32 * j;
        ap[j] = (r < cnt) ? (g_xt + (size_t)g_tok[e][r] * Hd + 4 * c) : nullptr;
    }
    int n4 = t & 15, kb = t >> 4;
    const float* bg = Bg + 4 * n4;
    const float* bu = Bu + 4 * n4;

    float accG[4][4][4], accU[4][4][4];
#pragma unroll
    for (int a = 0; a < 4; a++)
#pragma unroll
        for (int b = 0; b < 4; b++)
#pragma unroll
            for (int d = 0; d < 4; d++) { accG[a][b][d] = 0.f; accU[a][b][d] = 0.f; }

    float4 la[4], lg[2], lu[2];
    auto fetch = [&](int k0) {
#pragma unroll
        for (int j = 0; j < 4; j++)
            la[j] = ap[j] ? *(const float4*)(ap[j] + k0) : make_float4(0, 0, 0, 0);
#pragma unroll
        for (int j = 0; j < 2; j++) {
            lg[j] = *(const float4*)(bg + (size_t)(k0 + kb + 8 * j) * Ff);
            lu[j] = *(const float4*)(bu + (size_t)(k0 + kb + 8 * j) * Ff);
        }
    };
    auto stage = [&](int buf) {
#pragma unroll
        for (int j = 0; j < 4; j++)
            *(float4*)&sA[buf][(r0 + 32 * j) * 16 + 4 * c] = la[j];   // identity copy
#pragma unroll
        for (int j = 0; j < 2; j++) {
            *(float4*)&sG[buf][(kb + 8 * j) * 72 + 4 * n4] =
                make_float4(f2tf(lg[j].x), f2tf(lg[j].y), f2tf(lg[j].z), f2tf(lg[j].w));
            *(float4*)&sU[buf][(kb + 8 * j) * 72 + 4 * n4] =
                make_float4(f2tf(lu[j].x), f2tf(lu[j].y), f2tf(lu[j].z), f2tf(lu[j].w));
        }
    };

    fetch(0); stage(0);
    __syncthreads();
    const int KT = Hd / 16;   // 64
    for (int kt = 0; kt < KT; kt++) {
        int buf = kt & 1;
        if (kt + 1 < KT) fetch((kt + 1) * 16);

        uint4 alo[4], ahi[4];
#pragma unroll
        for (int mt = 0; mt < 4; mt++) {
            int R = wm * 64 + mt * 16 + qr;
            alo[mt] = *(const uint4*)&sA[buf][R * 16 + sfr];
            ahi[mt] = *(const uint4*)&sA[buf][(R + 8) * 16 + sfr];
        }
#pragma unroll
        for (int nth = 0; nth < 2; nth++) {
            unsigned bgf[2][2][2], buf2[2][2][2];
#pragma unroll
            for (int nt2 = 0; nt2 < 2; nt2++) {
                int n = wn * 32 + (nth * 2 + nt2) * 8 + qr;
#pragma unroll
                for (int ks = 0; ks < 2; ks++) {
                    bgf[nt2][ks][0] = *(const unsigned*)&sG[buf][(ks * 8 + qc) * 72 + n];
                    bgf[nt2][ks][1] = *(const unsigned*)&sG[buf][(ks * 8 + qc + 4) * 72 + n];
                    buf2[nt2][ks][0] = *(const unsigned*)&sU[buf][(ks * 8 + qc) * 72 + n];
                    buf2[nt2][ks][1] = *(const unsigned*)&sU[buf][(ks * 8 + qc + 4) * 72 + n];
                }
            }
#pragma unroll
            for (int nt2 = 0; nt2 < 2; nt2++) {
#pragma unroll
                for (int mt = 0; mt < 4; mt++)
                    mma8(accG[mt][nth * 2 + nt2], alo[mt].x, ahi[mt].x, alo[mt].y, ahi[mt].y,
                         bgf[nt2][0][0], bgf[nt2][0][1]);
#pragma unroll
                for (int mt = 0; mt < 4; mt++)
                    mma8(accG[mt][nth * 2 + nt2], alo[mt].z, ahi[mt].z, alo[mt].w, ahi[mt].w,
                         bgf[nt2][1][0], bgf[nt2][1][1]);
#pragma unroll
                for (int mt = 0; mt < 4; mt++)
                    mma8(accU[mt][nth * 2 + nt2], alo[mt].x, ahi[mt].x, alo[mt].y, ahi[mt].y,
                         buf2[nt2][0][0], buf2[nt2][0][1]);
#pragma unroll
                for (int mt = 0; mt < 4; mt++)
                    mma8(accU[mt][nth * 2 + nt2], alo[mt].z, ahi[mt].z, alo[mt].w, ahi[mt].w,
                         buf2[nt2][1][0], buf2[nt2][1][1]);
            }
        }
        if (kt + 1 < KT) stage(buf ^ 1);
        __syncthreads();
    }

    // epilogue: h = silu(g) * u -> g_h[tok*2+slot], tf32-rounded + k-interleaved
#pragma unroll
    for (int mt = 0; mt < 4; mt++) {
#pragma unroll
        for (int half = 0; half < 2; half++) {
            int r = row0 + wm * 64 + mt * 16 + qr + half * 8;
            if (r < cnt) {
                int aid = g_tok[e][r] * 2 + g_slot[e][r];
                float* hrow = g_h + (size_t)aid * Ff + col0;
#pragma unroll
                for (int nt = 0; nt < 4; nt++) {
                    float gg0 = accG[mt][nt][half * 2 + 0], gg1 = accG[mt][nt][half * 2 + 1];
                    float uu0 = accU[mt][nt][half * 2 + 0], uu1 = accU[mt][nt][half * 2 + 1];
                    float h0 = gg0 * uu0 / (1.f + __expf(-gg0));
                    float h1 = gg1 * uu1 / (1.f + __expf(-gg1));
                    int cc = wn * 32 + nt * 8 + 2 * qc;          // even
                    int i0 = cc & 15;
                    int w0 = (cc & ~15) + 4 * (i0 & 3) + (i0 >> 2);
                    hrow[w0]     = f2tf(h0);                     // i0
                    hrow[w0 + 4] = f2tf(h1);                     // i0+1
                }
            }
        }
    }
}

// ============================================================================
// GEMM2: block 128(M) x 128(N), 128 thr, warps 2x2 (tile 64x64)
// ============================================================================
__global__ void __launch_bounds__(128, 2) gemm2_kernel(const float* __restrict__ w_down)
{
    int e = blockIdx.z;
    int cnt = g_cnt[e];
    int row0 = blockIdx.y * 128;
    if (row0 >= cnt) return;
    int col0 = blockIdx.x * 128;
    const float* Bd = w_down + (size_t)e * Ff * Hd + col0;

    __shared__ __align__(16) float sA[2][128 * 16];
    __shared__ __align__(16) float sB[2][16 * 136];

    int t = threadIdx.x, lane = t & 31, warp = t >> 5;
    int wm = warp >> 1, wn = warp & 1;
    int qr = lane >> 2, qc = lane & 3;
    int sfr = 4 * qc;

    int c = t & 3, r0 = t >> 2;
    const float* ap[4];
#pragma unroll
    for (int j = 0; j < 4; j++) {
        int r = row0 + r0 + 32 * j;
        if (r < cnt) {
            int aid = g_tok[e][r] * 2 + g_slot[e][r];
            ap[j] = g_h + (size_t)aid * Ff + 4 * c;
        } else ap[j] = nullptr;
    }
    int n4 = lane, kb = warp;
    const float* bp = Bd + 4 * n4;

    float acc[4][8][4];
#pragma unroll
    for (int a = 0; a < 4; a++)
#pragma unroll
        for (int b = 0; b < 8; b++)
#pragma unroll
            for (int d = 0; d < 4; d++) acc[a][b][d] = 0.f;

    float4 la[4], lb[4];
    auto fetch = [&](int k0) {
#pragma unroll
        for (int j = 0; j < 4; j++)
            la[j] = ap[j] ? *(const float4*)(ap[j] + k0) : make_float4(0, 0, 0, 0);
#pragma unroll
        for (int j = 0; j < 4; j++)
            lb[j] = *(const float4*)(bp + (size_t)(k0 + kb + 4 * j) * Hd);
    };
    auto stage = [&](int buf) {
#pragma unroll
        for (int j = 0; j < 4; j++)
            *(float4*)&sA[buf][(r0 + 32 * j) * 16 + 4 * c] = la[j];   // identity copy
#pragma unroll
        for (int j = 0; j < 4; j++)
            *(float4*)&sB[buf][(kb + 4 * j) * 136 + 4 * n4] =
                make_float4(f2tf(lb[j].x), f2tf(lb[j].y), f2tf(lb[j].z), f2tf(lb[j].w));
    };

    fetch(0); stage(0);
    __syncthreads();
    const int KT = Ff / 16;   // 256
    for (int kt = 0; kt < KT; kt++) {
        int buf = kt & 1;
        if (kt + 1 < KT) fetch((kt + 1) * 16);

        uint4 alo[4], ahi[4];
#pragma unroll
        for (int mt = 0; mt < 4; mt++) {
            int R = wm * 64 + mt * 16 + qr;
            alo[mt] = *(const uint4*)&sA[buf][R * 16 + sfr];
            ahi[mt] = *(const uint4*)&sA[buf][(R + 8) * 16 + sfr];
        }
#pragma unroll
        for (int nth = 0; nth < 2; nth++) {
            unsigned bf[4][2][2];
#pragma unroll
            for (int nt2 = 0; nt2 < 4; nt2++) {
                int n = wn * 64 + (nth * 4 + nt2) * 8 + qr;
#pragma unroll
                for (int ks = 0; ks < 2; ks++) {
                    bf[nt2][ks][0] = *(const unsigned*)&sB[buf][(ks * 8 + qc) * 136 + n];
                    bf[nt2][ks][1] = *(const unsigned*)&sB[buf][(ks * 8 + qc + 4) * 136 + n];
                }
            }
#pragma unroll
            for (int nt2 = 0; nt2 < 4; nt2++) {
#pragma unroll
                for (int mt = 0; mt < 4; mt++)
                    mma8(acc[mt][nth * 4 + nt2], alo[mt].x, ahi[mt].x, alo[mt].y, ahi[mt].y,
                         bf[nt2][0][0], bf[nt2][0][1]);
#pragma unroll
                for (int mt = 0; mt < 4; mt++)
                    mma8(acc[mt][nth * 4 + nt2], alo[mt].z, ahi[mt].z, alo[mt].w, ahi[mt].w,
                         bf[nt2][1][0], bf[nt2][1][1]);
            }
        }
        if (kt + 1 < KT) stage(buf ^ 1);
        __syncthreads();
    }

#pragma unroll
    for (int mt = 0; mt < 4; mt++) {
#pragma unroll
        for (int half = 0; half < 2; half++) {
            int r = row0 + wm * 64 + mt * 16 + qr + half * 8;
            if (r < cnt) {
                int tok = g_tok[e][r];
                float w = g_wt[e][r];
                int sl  = g_slot[e][r];
                float* orow = g_sbuf + (size_t)sl * NT * Hd + (size_t)tok * Hd + col0;
#pragma unroll
                for (int nt = 0; nt < 8; nt++) {
                    int cc = wn * 64 + nt * 8 + 2 * qc;
                    *(float2*)(orow + cc) = make_float2(w * acc[mt][nt][half * 2 + 0],
                                                        w * acc[mt][nt][half * 2 + 1]);
                }
            }
        }
    }
}

__global__ void combine_kernel(float* __restrict__ out) {
    int i = blockIdx.x * 256 + threadIdx.x;
    if (i < NT * Hd / 4) {
        float4 a = ((const float4*)g_sbuf)[i];
        float4 b = ((const float4*)(g_sbuf + NT * Hd))[i];
        ((float4*)out)[i] = make_float4(a.x + b.x, a.y + b.y, a.z + b.z, a.w + b.w);
    }
}

// ---------------- launch ----------------
extern "C" void kernel_launch(void* const* d_in, const int* in_sizes, int n_in,
                              void* d_out, int out_size) {
    (void)in_sizes; (void)n_in; (void)out_size;
    const float* x      = (const float*)d_in[0];
    const float* gw     = (const float*)d_in[1];
    const float* w_gate = (const float*)d_in[2];
    const float* w_up   = (const float*)d_in[3];
    const float* w_down = (const float*)d_in[4];
    float* out = (float*)d_out;

    zero_kernel<<<1, 32>>>();
    xprep_kernel<<<(NT * Hd) / 256, 256>>>(x);
    router_kernel<<<NT / 8, 256>>>(x, gw);
    gemm1_kernel<<<dim3(Ff / 64, NT / 128, NE), 128>>>(w_gate, w_up);
    gemm2_kernel<<<dim3(Hd / 128, NT / 128, NE), 128>>>(w_down);
    combine_kernel<<<(NT * Hd / 4 + 255) / 256, 256>>>(out);
}